// round 5
// baseline (speedup 1.0000x reference)
#include <cuda_runtime.h>
#include <cuda_bf16.h>

// Device-global scratch (no allocations allowed).
__device__ float g_M1[100 * 100];       // level-1 partials (100 chunk matrices)
__device__ float g_c1[100 * 10];
__device__ float g_M3[100];             // final composed matrix [out][in]
__device__ float g_c3[10];              // final composed bias
__device__ unsigned g_ctr;              // fold-arrival counter (self-resetting)
__device__ volatile unsigned g_flag;    // fold-complete flag (self-resetting)
__device__ unsigned g_done;             // kernel-done counter (self-resetting)

#define TPB 256

// ---------------------------------------------------------------------------
// ONE persistent kernel (grid = 296 = 2 CTAs/SM, all resident):
//   CTAs 0..99 : fold 10 layers each; last arrival tree-reduces the 100
//                partials -> g_M3/g_c3, sets g_flag.
//   All CTAs   : spin on g_flag, then barrier-free coalesced apply using
//                warp-shuffle transpose (each lane owns ONE float4 of I/O).
// Affine combine rule (apply (M,c) then layer (Wn,bn)): M' = Wn@M, c' = Wn@c+bn.
// ---------------------------------------------------------------------------
__global__ void __launch_bounds__(TPB, 2) fused_kernel(const float* __restrict__ Ws,
                                                       const float* __restrict__ bs,
                                                       const float* __restrict__ x,
                                                       float* __restrict__ out,
                                                       long long pairs,
                                                       long long rows) {
    __shared__ float SH[11008];   // 44KB; phase B uses [0,11000); apply uses [0,110)
    __shared__ unsigned is_last;
    const int tid = threadIdx.x;
    const int cta = blockIdx.x;

    // ================= FOLD =================
    if (cta < 100) {
        // ---- Phase A: fold layers [10*cta, 10*cta+10) ----
        float* In  = SH;          // 10 x 100
        float* cIn = SH + 1000;   // 10 x 10
        float* M   = SH + 1100;   // 100
        float* cv  = SH + 1200;   // 10

        const float* mb = Ws + (size_t)cta * 1000;
        const float* cb = bs + (size_t)cta * 100;
        for (int idx = tid; idx < 1000; idx += TPB) In[idx]  = mb[idx];
        for (int idx = tid; idx < 100;  idx += TPB) cIn[idx] = cb[idx];
        __syncthreads();

        if (tid < 100) M[tid]  = In[tid];
        if (tid < 10)  cv[tid] = cIn[tid];
        __syncthreads();

        const int ei = (tid % 100) / 10;
        const int ej = tid % 10;

        #pragma unroll 1
        for (int l = 1; l < 10; ++l) {
            float nm = 0.f, nc = 0.f;
            const float* Wn = &In[l * 100];
            if (tid < 100) {
                #pragma unroll
                for (int k = 0; k < 10; ++k) nm += Wn[ei * 10 + k] * M[k * 10 + ej];
            }
            if (tid < 10) {
                nc = cIn[l * 10 + tid];
                #pragma unroll
                for (int k = 0; k < 10; ++k) nc += Wn[tid * 10 + k] * cv[k];
            }
            __syncthreads();
            if (tid < 100) M[tid]  = nm;
            if (tid < 10)  cv[tid] = nc;
            __syncthreads();
        }

        if (tid < 100) g_M1[cta * 100 + tid] = M[tid];
        if (tid < 10)  g_c1[cta * 10 + tid]  = cv[tid];

        __threadfence();
        __syncthreads();
        if (tid == 0) {
            unsigned old = atomicAdd(&g_ctr, 1u);
            is_last = (old == 99u) ? 1u : 0u;
        }
        __syncthreads();

        if (is_last) {
            __threadfence();
            // ---- Phase B: reduce 100 partials -> 1 ----
            float* SM = SH;           // 100 x 100
            float* SC = SH + 10000;   // 100 x 10
            for (int idx = tid; idx < 10000; idx += TPB) SM[idx] = g_M1[idx];
            for (int idx = tid; idx < 1000;  idx += TPB) SC[idx] = g_c1[idx];
            __syncthreads();

            // Level 2: 10 chains of 10 chunks. 2 groups of 100 threads, each
            // folds 5 chains sequentially (45 lockstep steps).
            const int g  = tid / 100;     // 0..1 active (tid < 200)
            const int e  = tid % 100;
            const int i2 = e / 10, j2 = e % 10;
            const bool act = (tid < 200);

            #pragma unroll 1
            for (int s = 0; s < 45; ++s) {
                const int d = g * 5 + s / 9;
                const int l = s % 9 + 1;
                float nm = 0.f, nc = 0.f;
                if (act) {
                    const float* W = &SM[(d * 10 + l) * 100];
                    const float* A = &SM[d * 1000];
                    #pragma unroll
                    for (int k = 0; k < 10; ++k) nm += W[i2 * 10 + k] * A[k * 10 + j2];
                    if (e < 10) {
                        nc = SC[(d * 10 + l) * 10 + e];
                        #pragma unroll
                        for (int k = 0; k < 10; ++k) nc += W[e * 10 + k] * SC[d * 100 + k];
                    }
                }
                __syncthreads();
                if (act) {
                    SM[d * 1000 + e] = nm;
                    if (e < 10) SC[d * 100 + e] = nc;
                }
                __syncthreads();
            }

            // Level 3: fold the 10 chain results in order.
            #pragma unroll 1
            for (int d = 1; d < 10; ++d) {
                float nm = 0.f, nc = 0.f;
                const float* W = &SM[d * 1000];
                if (tid < 100) {
                    #pragma unroll
                    for (int k = 0; k < 10; ++k) nm += W[i2 * 10 + k] * SM[k * 10 + j2];
                }
                if (tid < 10) {
                    nc = SC[d * 100 + tid];
                    #pragma unroll
                    for (int k = 0; k < 10; ++k) nc += W[tid * 10 + k] * SC[k];
                }
                __syncthreads();
                if (tid < 100) SM[tid] = nm;
                if (tid < 10)  SC[tid] = nc;
                __syncthreads();
            }

            if (tid < 100) g_M3[tid] = SM[tid];
            if (tid < 10)  g_c3[tid] = SC[tid];
            __syncthreads();
            __threadfence();
            if (tid == 0) {
                g_ctr  = 0;     // all 100 arrivals counted -> safe reset
                g_flag = 1;     // release
            }
        }
    }

    // ================= WAIT FOR FOLD =================
    if (tid == 0) {
        while (g_flag == 0u) __nanosleep(64);
    }
    __syncthreads();
    __threadfence();   // acquire

    // Composed affine -> smem (fold data in SH is dead by now).
    if (tid < 100) SH[tid]       = g_M3[tid];
    if (tid < 10)  SH[100 + tid] = g_c3[tid];
    __syncthreads();

    // ================= APPLY (barrier-free, warp-shuffle transpose) ==========
    // Warp tile = 30 contiguous float4 = 6 row-pairs. Lane owns float4 #lane
    // (lanes 30,31 idle on I/O but participate in shuffles).
    // phase = lane%5 selects which 4 output components this lane produces:
    //   lf = 4*phase + w  (w=0..3);  row1 iff lf>=10;  j = lf%10.
    const int lane  = tid & 31;
    const int phase = lane % 5;
    const int gbase = (lane / 5) * 5;
    const bool pA = (phase >= 3);   // outputs w=0,1 use row1 iff phase>=3
    const bool pB = (phase >= 2);   // outputs w=2,3 use row1 iff phase>=2

    // Per-lane M rows + biases into registers (constant-indexed thereafter).
    float mw[40], cw[4];
    #pragma unroll
    for (int w = 0; w < 4; ++w) {
        const int jw = (4 * phase + w) % 10;
        cw[w] = SH[100 + jw];
        #pragma unroll
        for (int k = 0; k < 10; ++k) mw[w * 10 + k] = SH[jw * 10 + k];
    }

    const long long nf4    = pairs * 5;
    const long long ntiles = (nf4 + 29) / 30;
    const long long nwarps = (long long)gridDim.x * (TPB / 32);
    const long long w0     = (long long)cta * (TPB / 32) + (tid >> 5);

    const float4* x4   = (const float4*)x;
    float4*       out4 = (float4*)out;

    long long t = w0;
    float4 v = make_float4(0.f, 0.f, 0.f, 0.f);
    {
        const long long g4 = t * 30 + lane;
        if (lane < 30 && t < ntiles && g4 < nf4) v = x4[g4];
    }

    for (; t < ntiles; t += nwarps) {
        // Prefetch next tile's float4 (independent of current compute).
        const long long tn = t + nwarps;
        float4 vn = make_float4(0.f, 0.f, 0.f, 0.f);
        {
            const long long g4n = tn * 30 + lane;
            if (lane < 30 && tn < ntiles && g4n < nf4) vn = x4[g4n];
        }

        // Gather the full 20-float pair from the 5-lane group (all static
        // register indices; src lane is runtime -> SHFL.IDX).
        float h[20];
        #pragma unroll
        for (int s = 0; s < 5; ++s) {
            const int src = gbase + s;
            h[4 * s + 0] = __shfl_sync(0xFFFFFFFFu, v.x, src);
            h[4 * s + 1] = __shfl_sync(0xFFFFFFFFu, v.y, src);
            h[4 * s + 2] = __shfl_sync(0xFFFFFFFFu, v.z, src);
            h[4 * s + 3] = __shfl_sync(0xFFFFFFFFu, v.w, src);
        }

        // 4 dot-products of length 10 with predicated row select (warp-uniform).
        float o0 = cw[0], o1 = cw[1], o2 = cw[2], o3 = cw[3];
        #pragma unroll
        for (int k = 0; k < 10; ++k) {
            const float ha = pA ? h[10 + k] : h[k];
            const float hb = pB ? h[10 + k] : h[k];
            o0 = fmaf(mw[k],      ha, o0);
            o1 = fmaf(mw[10 + k], ha, o1);
            o2 = fmaf(mw[20 + k], hb, o2);
            o3 = fmaf(mw[30 + k], hb, o3);
        }

        const long long g4 = t * 30 + lane;
        if (lane < 30 && g4 < nf4) out4[g4] = make_float4(o0, o1, o2, o3);

        v = vn;
    }

    // Odd-row tail (rows is even for this problem; kept for safety).
    if ((rows & 1LL) && cta == 0 && tid == 0) {
        const long long r = rows - 1;
        const float* xr = x + r * 10;
        float hh[10];
        #pragma unroll
        for (int k = 0; k < 10; ++k) hh[k] = xr[k];
        float* orow = out + r * 10;
        #pragma unroll
        for (int j = 0; j < 10; ++j) {
            float a = SH[100 + j];
            #pragma unroll
            for (int k = 0; k < 10; ++k) a += hh[k] * SH[j * 10 + k];
            orow[j] = a;
        }
    }

    // ================= RESET (replay-safe) =================
    __syncthreads();
    __threadfence();
    if (tid == 0) {
        const unsigned old = atomicAdd(&g_done, 1u);
        if (old == gridDim.x - 1) {   // every CTA fully done
            g_done = 0;
            g_flag = 0;
        }
    }
}

extern "C" void kernel_launch(void* const* d_in, const int* in_sizes, int n_in,
                              void* d_out, int out_size) {
    // Identify inputs by element count: x=BATCH*10, Ws=1000*100, bs=1000*10.
    const float* x  = nullptr;
    const float* Ws = nullptr;
    const float* bs = nullptr;
    long long x_elems = 0;
    for (int i = 0; i < n_in; ++i) {
        if (in_sizes[i] == 1000 * 100) {
            Ws = (const float*)d_in[i];
        } else if (in_sizes[i] == 1000 * 10) {
            bs = (const float*)d_in[i];
        } else {
            x = (const float*)d_in[i];
            x_elems = in_sizes[i];
        }
    }
    const long long rows  = x_elems / 10;
    const long long pairs = rows >> 1;

    // 296 CTAs = exactly 2/SM (launch_bounds guarantees residency) -> the whole
    // grid is wave-1, so the flag spin cannot deadlock, and CTAs 0..99 (fold)
    // are resident from the start.
    fused_kernel<<<296, TPB>>>(Ws, bs, x, (float*)d_out, pairs, rows);
}

// round 6
// speedup vs baseline: 1.6785x; 1.6785x over previous
#include <cuda_runtime.h>
#include <cuda_bf16.h>

// Device-global scratch (no allocations allowed).
__device__ float g_M1[100 * 100];  // level-1: 100 chunk matrices (10x10 each)
__device__ float g_c1[100 * 10];
__device__ float g_M2[10 * 100];   // level-2: 10 chunk matrices
__device__ float g_c2[10 * 10];
__device__ float g_M3[100];        // final composed matrix M (row-major [out][in])
__device__ float g_c3[10];         // final composed bias

// ---------------------------------------------------------------------------
// Fold PER consecutive affine maps (h -> h*W^T + b) into one. (R2 version.)
//   M' = Wn @ M ; c' = Wn @ c + bn
// ---------------------------------------------------------------------------
template <int PER>
__global__ void fold_kernel(const float* __restrict__ Min, const float* __restrict__ cin,
                            float* __restrict__ Mout, float* __restrict__ cout) {
    __shared__ float In[PER * 100];
    __shared__ float cIn[PER * 10];
    __shared__ float M[100];
    __shared__ float c[10];

    const int b   = blockIdx.x;
    const int tid = threadIdx.x;

    const float* mb = Min + (size_t)b * PER * 100;
    const float* cb = cin + (size_t)b * PER * 10;
    for (int idx = tid; idx < PER * 100; idx += blockDim.x) In[idx] = mb[idx];
    for (int idx = tid; idx < PER * 10; idx += blockDim.x) cIn[idx] = cb[idx];
    __syncthreads();

    if (tid < 100) M[tid] = In[tid];
    if (tid < 10)  c[tid] = cIn[tid];
    __syncthreads();

    const int i = tid / 10;
    const int j = tid % 10;

    #pragma unroll 1
    for (int l = 1; l < PER; ++l) {
        float nm = 0.f, nc = 0.f;
        if (tid < 100) {
            const float* Wn = &In[l * 100];
            #pragma unroll
            for (int k = 0; k < 10; ++k) nm += Wn[i * 10 + k] * M[k * 10 + j];
        }
        if (tid < 10) {
            const float* Wn = &In[l * 100];
            nc = cIn[l * 10 + tid];
            #pragma unroll
            for (int k = 0; k < 10; ++k) nc += Wn[tid * 10 + k] * c[k];
        }
        __syncthreads();
        if (tid < 100) M[tid] = nm;
        if (tid < 10)  c[tid] = nc;
        __syncthreads();
    }

    if (tid < 100) Mout[b * 100 + tid] = M[tid];
    if (tid < 10)  cout[b * 10 + tid]  = c[tid];
}

// ---------------------------------------------------------------------------
// PTX helpers (inline; cp.async.bulk 1D + mbarrier).
// ---------------------------------------------------------------------------
__device__ __forceinline__ unsigned smem_u32(const void* p) {
    unsigned r;
    asm("{ .reg .u64 t; cvta.to.shared.u64 t, %1; cvt.u32.u64 %0, t; }"
        : "=r"(r) : "l"(p));
    return r;
}
__device__ __forceinline__ void mbar_init(unsigned addr, unsigned count) {
    asm volatile("mbarrier.init.shared.b64 [%0], %1;" :: "r"(addr), "r"(count) : "memory");
}
__device__ __forceinline__ void mbar_expect_tx(unsigned addr, unsigned bytes) {
    asm volatile("mbarrier.arrive.expect_tx.shared.b64 _, [%0], %1;"
                 :: "r"(addr), "r"(bytes) : "memory");
}
__device__ __forceinline__ void bulk_load(unsigned dst_smem, const void* src_gmem,
                                          unsigned bytes, unsigned mbar) {
    asm volatile("cp.async.bulk.shared::cta.global.mbarrier::complete_tx::bytes "
                 "[%0], [%1], %2, [%3];"
                 :: "r"(dst_smem), "l"(src_gmem), "r"(bytes), "r"(mbar) : "memory");
}
__device__ __forceinline__ void mbar_wait(unsigned addr, unsigned parity) {
    unsigned done;
    asm volatile("{\n\t.reg .pred p;\n\t"
                 "mbarrier.try_wait.parity.acquire.cta.shared::cta.b64 p, [%1], %2;\n\t"
                 "selp.b32 %0, 1, 0, p;\n\t}"
                 : "=r"(done) : "r"(addr), "r"(parity) : "memory");
    while (!done) {
        asm volatile("{\n\t.reg .pred p;\n\t"
                     "mbarrier.try_wait.parity.acquire.cta.shared::cta.b64 p, [%1], %2, 0x989680;\n\t"
                     "selp.b32 %0, 1, 0, p;\n\t}"
                     : "=r"(done) : "r"(addr), "r"(parity) : "memory");
    }
}

// ---------------------------------------------------------------------------
// apply: out[r] = x[r] @ M^T + c, TMA-bulk pipelined.
//  - S=5 stages x 240 pairs (19200B) of smem, filled by cp.async.bulk (bypasses
//    L1tex -> no wavefront inflation; deep MLP via mbarrier ring, no LDG).
//  - Compute: 5-lane group owns one pair; lane reads its needed 20 floats via
//    LDS broadcasts (group banks {0,20,8,28,16,4}/+10 -> conflict-free) and
//    produces 4 consecutive output floats.
//  - Store: lanes 0..29 of a warp write 30 contiguous float4 (coalesced STG).
// ---------------------------------------------------------------------------
#define TPB 256
#define NSTAGE 5
#define STAGE_PAIRS 240              // 8 warps x 30 pairs
#define STAGE_BYTES (STAGE_PAIRS * 80)
#define STAGE_FLOATS (STAGE_PAIRS * 20)
#define BAR_FLOATS 256               // 1KB barrier area keeps stages 128B-aligned
#define APPLY_SMEM ((BAR_FLOATS + NSTAGE * STAGE_FLOATS) * 4)

__global__ void __launch_bounds__(TPB, 2) apply_kernel(const float* __restrict__ x,
                                                       float* __restrict__ out,
                                                       long long pairs,
                                                       long long rows) {
    extern __shared__ float SH[];
    const int tid = threadIdx.x;

    // mbarriers live in the first 1KB of smem (8B each).
    unsigned bar[NSTAGE];
    #pragma unroll
    for (int s = 0; s < NSTAGE; ++s) bar[s] = smem_u32(&SH[s * 2]);

    if (tid == 0) {
        #pragma unroll
        for (int s = 0; s < NSTAGE; ++s) mbar_init(bar[s], 1);
    }
    __syncthreads();

    const long long tiles = (pairs + STAGE_PAIRS - 1) / STAGE_PAIRS;
    const long long gstride = gridDim.x;
    const long long cta = blockIdx.x;

    // Prologue: issue NSTAGE bulk loads.
    if (tid == 0) {
        #pragma unroll
        for (int s = 0; s < NSTAGE; ++s) {
            const long long t = cta + (long long)s * gstride;
            if (t < tiles) {
                const long long pbase = t * STAGE_PAIRS;
                const unsigned np = (unsigned)((pairs - pbase < STAGE_PAIRS)
                                                 ? (pairs - pbase) : STAGE_PAIRS);
                const unsigned bytes = np * 80u;
                mbar_expect_tx(bar[s], bytes);
                bulk_load(smem_u32(&SH[BAR_FLOATS + s * STAGE_FLOATS]),
                          x + pbase * 20, bytes, bar[s]);
            }
        }
    }

    // Per-lane constants.
    const int lane  = tid & 31;
    const int warp  = tid >> 5;
    const int phase = lane % 5;
    const int lp    = lane / 5;            // group within warp (0..5; 6 for lanes 30/31)
    const bool active = (lane < 30);
    const int offA = (phase >= 3) ? 10 : 0;   // source row for outputs w=0,1
    const int offB = (phase >= 2) ? 10 : 0;   // source row for outputs w=2,3

    // Per-lane M rows + biases into registers (L1-resident after first hit).
    float mw[40], cw[4];
    #pragma unroll
    for (int w = 0; w < 4; ++w) {
        const int jw = (4 * phase + w) % 10;
        cw[w] = __ldg(&g_c3[jw]);
        #pragma unroll
        for (int k = 0; k < 10; ++k) mw[w * 10 + k] = __ldg(&g_M3[jw * 10 + k]);
    }

    float4* out4 = (float4*)out;

    // Main pipelined loop.
    long long i = 0;
    #pragma unroll 1
    for (long long t = cta; t < tiles; t += gstride, ++i) {
        const int s = (int)(i % NSTAGE);
        const unsigned parity = (unsigned)((i / NSTAGE) & 1);
        mbar_wait(bar[s], parity);

        const float* st = &SH[BAR_FLOATS + s * STAGE_FLOATS];
        const long long tb = t * STAGE_PAIRS;

        #pragma unroll
        for (int it = 0; it < 5; ++it) {
            const int p = warp * 30 + it * 6 + lp;
            const long long gp = tb + p;
            if (active && gp < pairs) {
                const float* rowA = st + p * 20 + offA;
                const float* rowB = st + p * 20 + offB;
                float o0 = cw[0], o1 = cw[1], o2 = cw[2], o3 = cw[3];
                #pragma unroll
                for (int k = 0; k < 10; ++k) {
                    const float a = rowA[k];
                    const float b = rowB[k];
                    o0 = fmaf(mw[k],      a, o0);
                    o1 = fmaf(mw[10 + k], a, o1);
                    o2 = fmaf(mw[20 + k], b, o2);
                    o3 = fmaf(mw[30 + k], b, o3);
                }
                out4[gp * 5 + phase] = make_float4(o0, o1, o2, o3);
            }
        }

        __syncthreads();   // all warps done with stage s
        const long long tn = t + (long long)NSTAGE * gstride;
        if (tn < tiles && tid == 0) {
            const long long pbase = tn * STAGE_PAIRS;
            const unsigned np = (unsigned)((pairs - pbase < STAGE_PAIRS)
                                             ? (pairs - pbase) : STAGE_PAIRS);
            const unsigned bytes = np * 80u;
            mbar_expect_tx(bar[s], bytes);
            bulk_load(smem_u32(&SH[BAR_FLOATS + s * STAGE_FLOATS]),
                      x + pbase * 20, bytes, bar[s]);
        }
    }

    // Odd-row tail (rows is even for this problem; kept for safety).
    if ((rows & 1LL) && blockIdx.x == 0 && tid == 0) {
        const long long r = rows - 1;
        const float* xr = x + r * 10;
        float h[10];
        #pragma unroll
        for (int k = 0; k < 10; ++k) h[k] = xr[k];
        float* orow = out + r * 10;
        #pragma unroll
        for (int j = 0; j < 10; ++j) {
            float a = __ldg(&g_c3[j]);
            #pragma unroll
            for (int k = 0; k < 10; ++k) a += h[k] * __ldg(&g_M3[j * 10 + k]);
            orow[j] = a;
        }
    }
}

extern "C" void kernel_launch(void* const* d_in, const int* in_sizes, int n_in,
                              void* d_out, int out_size) {
    // Identify inputs by element count: x=BATCH*10, Ws=1000*100, bs=1000*10.
    const float* x  = nullptr;
    const float* Ws = nullptr;
    const float* bs = nullptr;
    long long x_elems = 0;
    for (int i = 0; i < n_in; ++i) {
        if (in_sizes[i] == 1000 * 100) {
            Ws = (const float*)d_in[i];
        } else if (in_sizes[i] == 1000 * 10) {
            bs = (const float*)d_in[i];
        } else {
            x = (const float*)d_in[i];
            x_elems = in_sizes[i];
        }
    }
    const long long rows  = x_elems / 10;
    const long long pairs = rows >> 1;

    float *M1, *c1, *M2, *c2, *M3, *c3;
    cudaGetSymbolAddress((void**)&M1, g_M1);
    cudaGetSymbolAddress((void**)&c1, g_c1);
    cudaGetSymbolAddress((void**)&M2, g_M2);
    cudaGetSymbolAddress((void**)&c2, g_c2);
    cudaGetSymbolAddress((void**)&M3, g_M3);
    cudaGetSymbolAddress((void**)&c3, g_c3);

    // Compose 1000 affines -> 1 affine via 3-level tree (10 each).
    fold_kernel<10><<<100, 128>>>(Ws, bs, M1, c1);
    fold_kernel<10><<<10, 128>>>(M1, c1, M2, c2);
    fold_kernel<10><<<1, 128>>>(M2, c2, M3, c3);

    // TMA-pipelined streaming apply: 296 CTAs = 2/SM, 97KB dynamic smem each.
    static int smem_set = 0;
    if (!smem_set) {
        cudaFuncSetAttribute(apply_kernel,
                             cudaFuncAttributeMaxDynamicSharedMemorySize, APPLY_SMEM);
        smem_set = 1;
    }
    apply_kernel<<<296, TPB, APPLY_SMEM>>>(x, (float*)d_out, pairs, rows);
}